// round 14
// baseline (speedup 1.0000x reference)
#include <cuda_runtime.h>
#include <cuda_fp16.h>
#include <math_constants.h>
#include <cstdint>

// Problem constants
#define NLAG   12
#define NB     32
#define NN     1200
#define MROWS  1152          // 3 * NLAG * NB
#define KDIM   1200
#define KP     1216          // K padded to 19*64
#define NP     1280          // B storage width (padded)

// GEMM tiling: CTA 128m x 80n, BK=64, 256 threads (8 warps = 4m x 2n, 32x40)
#define BK      64
#define NCHUNK  (KP / BK)    // 19
#define AROWB   144
#define BROWB   176
#define A_TILE  (128 * AROWB)    // 18432
#define B_TILE  (64 * BROWB)     // 11264
#define OFF_A0  0
#define OFF_B0  A_TILE
#define STAGE   (A_TILE + B_TILE)   // 29696
#define NSTAGES 3
#define NUNITS  1664

#define NCTAS   135              // (15, 9) grid — one wave, all co-resident
#define NT      (NCTAS * 256)    // 34560 grid threads

// Scratch (device globals; no allocation allowed)
__device__ __align__(16) __half g_A0[MROWS * KP];
__device__ __align__(16) __half g_B0[KP * NP];    // k-major
__device__ __align__(16) float g_C[MROWS * NN];
__device__ float g_belta[NLAG];
__device__ float g_c2[NLAG];
__device__ float g_pf[NLAG];

// Grid-barrier state (self-resetting each launch)
__device__ int          g_ctr  = 0;
__device__ int          g_done = 0;
__device__ volatile int g_release = 0;

// ---------------------------------------------------------------------------
__device__ __forceinline__ uint32_t smem_u32(const void* p) {
    uint32_t a;
    asm("{ .reg .u64 t; cvta.to.shared.u64 t, %1; cvt.u32.u64 %0, t; }"
        : "=r"(a) : "l"(p));
    return a;
}

#define LDSM4(r, addr)                                                      \
    asm volatile("ldmatrix.sync.aligned.m8n8.x4.shared.b16 "                \
                 "{%0, %1, %2, %3}, [%4];"                                  \
                 : "=r"((r)[0]), "=r"((r)[1]), "=r"((r)[2]), "=r"((r)[3])   \
                 : "r"(addr))
#define LDSM4T(r, addr)                                                     \
    asm volatile("ldmatrix.sync.aligned.m8n8.x4.trans.shared.b16 "          \
                 "{%0, %1, %2, %3}, [%4];"                                  \
                 : "=r"((r)[0]), "=r"((r)[1]), "=r"((r)[2]), "=r"((r)[3])   \
                 : "r"(addr))
#define LDSM2T(r, addr)                                                     \
    asm volatile("ldmatrix.sync.aligned.m8n8.x2.trans.shared.b16 "          \
                 "{%0, %1}, [%2];"                                          \
                 : "=r"((r)[0]), "=r"((r)[1]) : "r"(addr))

#define MMA_F16(c, a, bb0, bb1)                                             \
    asm volatile("mma.sync.aligned.m16n8k16.row.col.f32.f16.f16.f32 "       \
                 "{%0, %1, %2, %3}, {%4, %5, %6, %7}, {%8, %9}, "           \
                 "{%0, %1, %2, %3};"                                        \
                 : "+f"((c)[0]), "+f"((c)[1]), "+f"((c)[2]), "+f"((c)[3])   \
                 : "r"((a)[0]), "r"((a)[1]), "r"((a)[2]), "r"((a)[3]),      \
                   "r"(bb0), "r"(bb1))

#define CP_ASYNC16(dst, src)                                                \
    asm volatile("cp.async.cg.shared.global [%0], [%1], 16;"                \
                 :: "r"(dst), "l"(__cvta_generic_to_global(src)))
#define CP_COMMIT() asm volatile("cp.async.commit_group;" ::: "memory")
#define CP_WAIT1()  asm volatile("cp.async.wait_group 1;" ::: "memory")
#define CP_WAIT0()  asm volatile("cp.async.wait_group 0;" ::: "memory")

// ---------------------------------------------------------------------------
__device__ __forceinline__ float gamma_fn(float x) {
    if (x > 0.f) return expf(lgammaf(x));
    return CUDART_PI_F / (sinf(CUDART_PI_F * x) * expf(lgammaf(1.f - x)));
}

__device__ __forceinline__ uint32_t pack4h(float a, float b, float c, float d,
                                           uint32_t& hi) {
    __half2 lo2 = __halves2half2(__float2half(a), __float2half(b));
    __half2 hi2 = __halves2half2(__float2half(c), __float2half(d));
    hi = *reinterpret_cast<uint32_t*>(&hi2);
    return *reinterpret_cast<uint32_t*>(&lo2);
}

// Grid barrier: all NCTAS CTAs arrive, then proceed. phase = 1, 2, ...
__device__ __forceinline__ void grid_barrier(int phase) {
    __syncthreads();
    if (threadIdx.x == 0) {
        __threadfence();
        atomicAdd(&g_ctr, 1);
        if (atomicAdd(&g_ctr, 0) >= NCTAS * phase) g_release = phase;
        while (g_release < phase) {
            if (atomicAdd(&g_ctr, 0) >= NCTAS * phase) g_release = phase;
        }
        __threadfence();
    }
    __syncthreads();
}

// ---------------------------------------------------------------------------
// Prep section sizes
#define R0 (384 * KP / 4)
#define R1 (NB * NN / 2)
#define R2 (768 * (KP - KDIM) / 4)
#define R3 (KP * NP / 4)

// cp.async issue for one chunk: B 64x160B (640 units); A 128x128B (1024 units)
__device__ __forceinline__ void issue_chunk(uint32_t stage, int m0, int n0,
                                            int k0, int tid) {
#pragma unroll
    for (int i = 0; i < 7; i++) {
        int u = tid + i * 256;
        if (u < NUNITS) {
            uint32_t dst;
            const __half* src;
            if (u < 640) {
                int row = u / 10;
                int seg = u - row * 10;
                src = g_B0 + (size_t)(k0 + row) * NP + n0 + seg * 8;
                dst = stage + OFF_B0 + row * BROWB + seg * 16;
            } else {
                int v   = u - 640;
                int row = v >> 3;
                int seg = v & 7;
                src = g_A0 + (size_t)(m0 + row) * KP + k0 + seg * 8;
                dst = stage + OFF_A0 + row * AROWB + seg * 16;
            }
            CP_ASYNC16(dst, src);
        }
    }
}

// ---------------------------------------------------------------------------
// Fused persistent kernel: prep -> barrier -> GEMM -> barrier -> epilogue.
// Grid (15, 9) = 135 CTAs, one per SM, all co-resident (barrier-safe).
// ---------------------------------------------------------------------------
__global__ __launch_bounds__(256)
void fused_kernel(const float* __restrict__ A,
                  const float* __restrict__ WW,
                  const float* __restrict__ train_init,
                  const float* __restrict__ alpha,
                  const float* __restrict__ fract,
                  const float* __restrict__ lambd,
                  const float* __restrict__ l,
                  float* __restrict__ out) {
    extern __shared__ __align__(16) char smem[];
    const int tid  = threadIdx.x;
    const int cta  = blockIdx.y * 15 + blockIdx.x;
    const int gtid = cta * 256 + tid;

    // ---------------- Phase 0: prep -------------------------------------
    if (gtid < NLAG) {
        int lag = gtid;
        float a   = alpha[lag];
        float f   = fract[lag];
        float ga1 = gamma_fn(a + 1.f);
        float gm2 = gamma_fn(a - 2.f);
        float belta = 1.f
                    + ga1 / gamma_fn(a)
                    + ga1 / (2.f * gamma_fn(a - 1.f))
                    + ga1 / (6.f * gm2);
        g_belta[lag] = belta;
        g_c2[lag]    = ga1 / (6.f * gm2);
        g_pf[lag]    = 2.f * powf(3.f, f);
    }

    // A slice rows [0,384): float4 -> 4 fp16
#pragma unroll 2
    for (int idx = gtid; idx < R0; idx += NT) {
        int r = idx / (KP / 4);
        int k = (idx - r * (KP / 4)) * 4;
        float4 v = make_float4(0.f, 0.f, 0.f, 0.f);
        if (k < KDIM)
            v = *reinterpret_cast<const float4*>(&A[r * KDIM + k]);
        uint32_t hi, lo = pack4h(v.x, v.y, v.z, v.w, hi);
        reinterpret_cast<uint2*>(g_A0)[idx] = make_uint2(lo, hi);
    }

    // train_init gather: one thread per (b, i-pair)
    for (int p = gtid; p < R1; p += NT) {
        int b = p / (NN / 2);
        int i = (p - b * (NN / 2)) * 2;
        const float4* ti4 = reinterpret_cast<const float4*>(
            train_init + (size_t)(b * NN + i) * 26);
        float buf[52];
#pragma unroll
        for (int q = 0; q < 13; q++) {
            float4 v = ti4[q];
            buf[q * 4 + 0] = v.x; buf[q * 4 + 1] = v.y;
            buf[q * 4 + 2] = v.z; buf[q * 4 + 3] = v.w;
        }
#pragma unroll
        for (int j = 0; j < 13; j++) {
            __half2 h = __halves2half2(__float2half(buf[2 * j + 1]),
                                       __float2half(buf[26 + 2 * j + 1]));
            if (j >= 1) {
                int row = 384 + (j - 1) * NB + b;
                *reinterpret_cast<__half2*>(&g_A0[(size_t)row * KP + i]) = h;
            }
            if (j <= 11) {
                int row = 768 + j * NB + b;
                *reinterpret_cast<__half2*>(&g_A0[(size_t)row * KP + i]) = h;
            }
        }
    }

    // zero-fill k padding rows [384,1152)
    for (int p = gtid; p < R2; p += NT) {
        int padw = (KP - KDIM) / 4;
        int row = 384 + p / padw;
        int k   = KDIM + (p % padw) * 4;
        reinterpret_cast<uint2*>(&g_A0[(size_t)row * KP + k])[0] = make_uint2(0u, 0u);
    }

    // B pack (k-major fp16)
#pragma unroll 4
    for (int p = gtid; p < R3; p += NT) {
        int k = p / (NP / 4);
        int n = (p - k * (NP / 4)) * 4;
        float4 v = make_float4(0.f, 0.f, 0.f, 0.f);
        if (k < KDIM && n < NN)
            v = *reinterpret_cast<const float4*>(&WW[k * NN + n]);
        uint32_t hi, lo = pack4h(v.x, v.y, v.z, v.w, hi);
        reinterpret_cast<uint2*>(g_B0)[p] = make_uint2(lo, hi);
    }

    grid_barrier(1);

    // ---------------- Phase 1: GEMM (R13 body) --------------------------
    {
        const uint32_t sb = smem_u32(smem);
        const int lane = tid & 31;
        const int wid  = tid >> 5;
        const int wm   = wid & 3;
        const int wn   = wid >> 2;
        const int m0   = blockIdx.y * 128;
        const int n0   = blockIdx.x * 80;

        const int j = lane >> 3, rr = lane & 7;
        const uint32_t a_off  = (uint32_t)((wm * 32 + (j & 1) * 8 + rr) * AROWB + (j >> 1) * 16);
        const uint32_t b4_off = (uint32_t)(((j & 1) * 8 + rr) * BROWB + (j >> 1) * 16 + wn * 80);
        const uint32_t b2_off = (uint32_t)(((j & 1) * 8 + rr) * BROWB + wn * 80 + 64);

        float acc[2][5][4];
#pragma unroll
        for (int mf = 0; mf < 2; mf++)
#pragma unroll
            for (int f = 0; f < 5; f++)
#pragma unroll
                for (int e = 0; e < 4; e++) acc[mf][f][e] = 0.f;

        issue_chunk(sb + 0 * STAGE, m0, n0, 0, tid);
        CP_COMMIT();
        issue_chunk(sb + 1 * STAGE, m0, n0, BK, tid);
        CP_COMMIT();

        int cur = 0, nx2 = 2;
        for (int c = 0; c < NCHUNK; c++) {
            if (c + 1 < NCHUNK) CP_WAIT1(); else CP_WAIT0();
            __syncthreads();

            if (c + 2 < NCHUNK) {
                issue_chunk(sb + (uint32_t)nx2 * STAGE, m0, n0, (c + 2) * BK, tid);
                CP_COMMIT();
            }

            const uint32_t stage = sb + (uint32_t)cur * STAGE;
#pragma unroll
            for (int ks = 0; ks < 4; ks++) {
                uint32_t A0f[4], A1f[4];
                LDSM4(A0f, stage + OFF_A0 + a_off + ks * 32);
                LDSM4(A1f, stage + OFF_A0 + a_off + 16 * AROWB + ks * 32);
                uint32_t B0r[10];
                LDSM4T(&B0r[0], stage + OFF_B0 + b4_off + ks * 16 * BROWB);
                LDSM4T(&B0r[4], stage + OFF_B0 + b4_off + 32 + ks * 16 * BROWB);
                LDSM2T(&B0r[8], stage + OFF_B0 + b2_off + ks * 16 * BROWB);
#pragma unroll
                for (int f = 0; f < 5; f++) {
                    MMA_F16(acc[0][f], A0f, B0r[2 * f], B0r[2 * f + 1]);
                    MMA_F16(acc[1][f], A1f, B0r[2 * f], B0r[2 * f + 1]);
                }
            }

            cur = (cur + 1 == NSTAGES) ? 0 : cur + 1;
            nx2 = (nx2 + 1 == NSTAGES) ? 0 : nx2 + 1;
        }

        // Store with fused tanh(-x)
        const int gid = lane >> 2, tig = lane & 3;
#pragma unroll
        for (int mf = 0; mf < 2; mf++) {
            const int row = m0 + wm * 32 + mf * 16 + gid;
            float* c0p = &g_C[(size_t)row * NN];
            float* c1p = &g_C[(size_t)(row + 8) * NN];
#pragma unroll
            for (int f = 0; f < 5; f++) {
                int col = n0 + wn * 40 + f * 8 + tig * 2;
                float2 lo, hi;
                lo.x = tanhf(-acc[mf][f][0]);
                lo.y = tanhf(-acc[mf][f][1]);
                hi.x = tanhf(-acc[mf][f][2]);
                hi.y = tanhf(-acc[mf][f][3]);
                *reinterpret_cast<float2*>(c0p + col) = lo;
                *reinterpret_cast<float2*>(c1p + col) = hi;
            }
        }
    }

    grid_barrier(2);

    // ---------------- Phase 2: epilogue ---------------------------------
    const int total4 = NB * NLAG * (NN / 4);
    for (int idx = gtid; idx < total4; idx += NT) {
        int j4  = (idx % (NN / 4)) * 4;
        int lag = (idx / (NN / 4)) % NLAG;
        int b   = idx / ((NN / 4) * NLAG);
        int jm  = j4 % 200;

        int r = lag * NB + b;
        float4 o4 = *reinterpret_cast<const float4*>(&g_C[(size_t)r * NN + j4]);
        float4 a4 = *reinterpret_cast<const float4*>(&g_C[(size_t)(384 + r) * NN + j4]);
        float4 n4 = *reinterpret_cast<const float4*>(&g_C[(size_t)(768 + r) * NN + j4]);
        float4 lam = *reinterpret_cast<const float4*>(&lambd[lag * 200 + jm]);
        float4 lv  = *reinterpret_cast<const float4*>(&l[lag * 200 + jm]);

        float ib = 1.f / g_belta[lag];
        float pf = g_pf[lag];
        float c2 = g_c2[lag];

        float4 o;
        o.x = lam.x * ib * (pf * o4.x + 3.f * lv.x * (a4.x + c2 * n4.x));
        o.y = lam.y * ib * (pf * o4.y + 3.f * lv.y * (a4.y + c2 * n4.y));
        o.z = lam.z * ib * (pf * o4.z + 3.f * lv.z * (a4.z + c2 * n4.z));
        o.w = lam.w * ib * (pf * o4.w + 3.f * lv.w * (a4.w + c2 * n4.w));
        *reinterpret_cast<float4*>(&out[(size_t)idx * 4]) = o;
    }

    // ---------------- Reset barrier state for next launch ----------------
    __syncthreads();
    if (tid == 0) {
        int old = atomicAdd(&g_done, 1);
        if (old == NCTAS - 1) {
            g_ctr  = 0;
            g_done = 0;
            g_release = 0;
            __threadfence();
        }
    }
}

// ---------------------------------------------------------------------------
extern "C" void kernel_launch(void* const* d_in, const int* in_sizes, int n_in,
                              void* d_out, int out_size) {
    const float* A          = (const float*)d_in[0];
    const float* WW         = (const float*)d_in[1];
    const float* train_init = (const float*)d_in[2];
    const float* alpha      = (const float*)d_in[3];
    const float* fract      = (const float*)d_in[4];
    const float* lambd      = (const float*)d_in[5];
    const float* l          = (const float*)d_in[6];
    float* out = (float*)d_out;

    cudaFuncSetAttribute(fused_kernel,
                         cudaFuncAttributeMaxDynamicSharedMemorySize,
                         NSTAGES * STAGE);

    dim3 ggrid(15, 9);                            // 135 CTAs, one wave
    fused_kernel<<<ggrid, 256, NSTAGES * STAGE>>>(
        A, WW, train_init, alpha, fract, lambd, l, out);
}

// round 15
// speedup vs baseline: 1.7006x; 1.7006x over previous
#include <cuda_runtime.h>
#include <cuda_fp16.h>
#include <math_constants.h>
#include <cstdint>

// Problem constants
#define NLAG   12
#define NB     32
#define NN     1200
#define MROWS  1152          // 3 * NLAG * NB
#define KDIM   1200
#define KP     1216          // K padded to 19*64
#define NP     1280          // B storage width (padded)

// GEMM tiling: CTA 128m x 80n, BK=64, 256 threads (8 warps = 4m x 2n, 32x40)
#define BK      64
#define NCHUNK  (KP / BK)    // 19
#define AROWB   144
#define BROWB   176
#define A_TILE  (128 * AROWB)    // 18432
#define B_TILE  (64 * BROWB)     // 11264
#define OFF_A0  0
#define OFF_B0  A_TILE
#define STAGE   (A_TILE + B_TILE)   // 29696
#define NSTAGES 3
#define NUNITS  1664

// Scratch (device globals; no allocation allowed)
__device__ __align__(16) __half g_A0[MROWS * KP];
__device__ __align__(16) __half g_B0[KP * NP];    // k-major
__device__ __align__(16) float g_C[MROWS * NN];
__device__ float g_belta[NLAG];
__device__ float g_c2[NLAG];
__device__ float g_pf[NLAG];
// Per-output-region arrival counters (reset by the combiner each launch)
__device__ int g_cnt[3][15];

// ---------------------------------------------------------------------------
__device__ __forceinline__ uint32_t smem_u32(const void* p) {
    uint32_t a;
    asm("{ .reg .u64 t; cvta.to.shared.u64 t, %1; cvt.u32.u64 %0, t; }"
        : "=r"(a) : "l"(p));
    return a;
}

#define LDSM4(r, addr)                                                      \
    asm volatile("ldmatrix.sync.aligned.m8n8.x4.shared.b16 "                \
                 "{%0, %1, %2, %3}, [%4];"                                  \
                 : "=r"((r)[0]), "=r"((r)[1]), "=r"((r)[2]), "=r"((r)[3])   \
                 : "r"(addr))
#define LDSM4T(r, addr)                                                     \
    asm volatile("ldmatrix.sync.aligned.m8n8.x4.trans.shared.b16 "          \
                 "{%0, %1, %2, %3}, [%4];"                                  \
                 : "=r"((r)[0]), "=r"((r)[1]), "=r"((r)[2]), "=r"((r)[3])   \
                 : "r"(addr))
#define LDSM2T(r, addr)                                                     \
    asm volatile("ldmatrix.sync.aligned.m8n8.x2.trans.shared.b16 "          \
                 "{%0, %1}, [%2];"                                          \
                 : "=r"((r)[0]), "=r"((r)[1]) : "r"(addr))

#define MMA_F16(c, a, bb0, bb1)                                             \
    asm volatile("mma.sync.aligned.m16n8k16.row.col.f32.f16.f16.f32 "       \
                 "{%0, %1, %2, %3}, {%4, %5, %6, %7}, {%8, %9}, "           \
                 "{%0, %1, %2, %3};"                                        \
                 : "+f"((c)[0]), "+f"((c)[1]), "+f"((c)[2]), "+f"((c)[3])   \
                 : "r"((a)[0]), "r"((a)[1]), "r"((a)[2]), "r"((a)[3]),      \
                   "r"(bb0), "r"(bb1))

#define CP_ASYNC16(dst, src)                                                \
    asm volatile("cp.async.cg.shared.global [%0], [%1], 16;"                \
                 :: "r"(dst), "l"(__cvta_generic_to_global(src)))
#define CP_COMMIT() asm volatile("cp.async.commit_group;" ::: "memory")
#define CP_WAIT1()  asm volatile("cp.async.wait_group 1;" ::: "memory")
#define CP_WAIT0()  asm volatile("cp.async.wait_group 0;" ::: "memory")

// ---------------------------------------------------------------------------
__device__ __forceinline__ float gamma_fn(float x) {
    if (x > 0.f) return expf(lgammaf(x));
    return CUDART_PI_F / (sinf(CUDART_PI_F * x) * expf(lgammaf(1.f - x)));
}

__device__ __forceinline__ uint32_t pack4h(float a, float b, float c, float d,
                                           uint32_t& hi) {
    __half2 lo2 = __halves2half2(__float2half(a), __float2half(b));
    __half2 hi2 = __halves2half2(__float2half(c), __float2half(d));
    hi = *reinterpret_cast<uint32_t*>(&hi2);
    return *reinterpret_cast<uint32_t*>(&lo2);
}

// ---------------------------------------------------------------------------
// Fused prep (R13/R11 layout; unchanged — runs at high occupancy standalone)
// ---------------------------------------------------------------------------
#define R0 (384 * KP / 4)
#define R1 (NB * NN / 2)
#define R2 (768 * (KP - KDIM) / 4)
#define R3 (KP * NP / 4)
#define PREP_TOTAL (R0 + R1 + R2 + R3)

__global__ void prep_kernel(const float* __restrict__ A,
                            const float* __restrict__ WW,
                            const float* __restrict__ train_init,
                            const float* __restrict__ alpha,
                            const float* __restrict__ fract) {
    int idx = blockIdx.x * blockDim.x + threadIdx.x;

    if (blockIdx.x == 0 && threadIdx.x < NLAG) {
        int lag = threadIdx.x;
        float a   = alpha[lag];
        float f   = fract[lag];
        float ga1 = gamma_fn(a + 1.f);
        float gm2 = gamma_fn(a - 2.f);
        float belta = 1.f
                    + ga1 / gamma_fn(a)
                    + ga1 / (2.f * gamma_fn(a - 1.f))
                    + ga1 / (6.f * gm2);
        g_belta[lag] = belta;
        g_c2[lag]    = ga1 / (6.f * gm2);
        g_pf[lag]    = 2.f * powf(3.f, f);
    }

    if (idx < R0) {
        int r = idx / (KP / 4);
        int k = (idx - r * (KP / 4)) * 4;
        float4 v = make_float4(0.f, 0.f, 0.f, 0.f);
        if (k < KDIM)
            v = *reinterpret_cast<const float4*>(&A[r * KDIM + k]);
        uint32_t hi, lo = pack4h(v.x, v.y, v.z, v.w, hi);
        reinterpret_cast<uint2*>(g_A0)[idx] = make_uint2(lo, hi);
    } else if (idx < R0 + R1) {
        int p = idx - R0;
        int b = p / (NN / 2);
        int i = (p - b * (NN / 2)) * 2;
        const float4* ti4 = reinterpret_cast<const float4*>(
            train_init + (size_t)(b * NN + i) * 26);
        float buf[52];
#pragma unroll
        for (int q = 0; q < 13; q++) {
            float4 v = ti4[q];
            buf[q * 4 + 0] = v.x; buf[q * 4 + 1] = v.y;
            buf[q * 4 + 2] = v.z; buf[q * 4 + 3] = v.w;
        }
#pragma unroll
        for (int j = 0; j < 13; j++) {
            __half2 h = __halves2half2(__float2half(buf[2 * j + 1]),
                                       __float2half(buf[26 + 2 * j + 1]));
            if (j >= 1) {
                int row = 384 + (j - 1) * NB + b;
                *reinterpret_cast<__half2*>(&g_A0[(size_t)row * KP + i]) = h;
            }
            if (j <= 11) {
                int row = 768 + j * NB + b;
                *reinterpret_cast<__half2*>(&g_A0[(size_t)row * KP + i]) = h;
            }
        }
    } else if (idx < R0 + R1 + R2) {
        int p = idx - R0 - R1;
        int padw = (KP - KDIM) / 4;
        int row = 384 + p / padw;
        int k   = KDIM + (p % padw) * 4;
        reinterpret_cast<uint2*>(&g_A0[(size_t)row * KP + k])[0] = make_uint2(0u, 0u);
    } else if (idx < PREP_TOTAL) {
        int p = idx - R0 - R1 - R2;
        int k = p / (NP / 4);
        int n = (p - k * (NP / 4)) * 4;
        float4 v = make_float4(0.f, 0.f, 0.f, 0.f);
        if (k < KDIM && n < NN)
            v = *reinterpret_cast<const float4*>(&WW[k * NN + n]);
        uint32_t hi, lo = pack4h(v.x, v.y, v.z, v.w, hi);
        reinterpret_cast<uint2*>(g_B0)[p] = make_uint2(lo, hi);
    }
}

// ---------------------------------------------------------------------------
// cp.async issue for one chunk: B 64x160B (640 units); A 128x128B (1024 units)
// ---------------------------------------------------------------------------
__device__ __forceinline__ void issue_chunk(uint32_t stage, int m0, int n0,
                                            int k0, int tid) {
#pragma unroll
    for (int i = 0; i < 7; i++) {
        int u = tid + i * 256;
        if (u < NUNITS) {
            uint32_t dst;
            const __half* src;
            if (u < 640) {
                int row = u / 10;
                int seg = u - row * 10;
                src = g_B0 + (size_t)(k0 + row) * NP + n0 + seg * 8;
                dst = stage + OFF_B0 + row * BROWB + seg * 16;
            } else {
                int v   = u - 640;
                int row = v >> 3;
                int seg = v & 7;
                src = g_A0 + (size_t)(m0 + row) * KP + k0 + seg * 8;
                dst = stage + OFF_A0 + row * AROWB + seg * 16;
            }
            CP_ASYNC16(dst, src);
        }
    }
}

// ---------------------------------------------------------------------------
// fp16 HMMA GEMM + fused combine-on-last-arrival.
// CTA 128x80, 8 warps (32m x 40n each), BK=64, 3-stage cp.async pipeline.
// Grid (15, 9) = 135 CTAs, one wave. Output region (x, y%3) combined by the
// third of CTAs {(x,y),(x,y+3),(x,y+6)} to finish (atomic counter handoff).
// ---------------------------------------------------------------------------
__global__ __launch_bounds__(256)
void gemm_mma_kernel(const float* __restrict__ lambd,
                     const float* __restrict__ l,
                     float* __restrict__ out) {
    extern __shared__ __align__(16) char smem[];
    const uint32_t sb = smem_u32(smem);
    const int tid  = threadIdx.x;
    const int lane = tid & 31;
    const int wid  = tid >> 5;
    const int wm   = wid & 3;
    const int wn   = wid >> 2;
    const int m0   = blockIdx.y * 128;
    const int n0   = blockIdx.x * 80;

    const int j = lane >> 3, rr = lane & 7;
    const uint32_t a_off  = (uint32_t)((wm * 32 + (j & 1) * 8 + rr) * AROWB + (j >> 1) * 16);
    const uint32_t b4_off = (uint32_t)(((j & 1) * 8 + rr) * BROWB + (j >> 1) * 16 + wn * 80);
    const uint32_t b2_off = (uint32_t)(((j & 1) * 8 + rr) * BROWB + wn * 80 + 64);

    float acc[2][5][4];
#pragma unroll
    for (int mf = 0; mf < 2; mf++)
#pragma unroll
        for (int f = 0; f < 5; f++)
#pragma unroll
            for (int e = 0; e < 4; e++) acc[mf][f][e] = 0.f;

    issue_chunk(sb + 0 * STAGE, m0, n0, 0, tid);
    CP_COMMIT();
    issue_chunk(sb + 1 * STAGE, m0, n0, BK, tid);
    CP_COMMIT();

    int cur = 0, nx2 = 2;
    for (int c = 0; c < NCHUNK; c++) {
        if (c + 1 < NCHUNK) CP_WAIT1(); else CP_WAIT0();
        __syncthreads();

        if (c + 2 < NCHUNK) {
            issue_chunk(sb + (uint32_t)nx2 * STAGE, m0, n0, (c + 2) * BK, tid);
            CP_COMMIT();
        }

        const uint32_t stage = sb + (uint32_t)cur * STAGE;
#pragma unroll
        for (int ks = 0; ks < 4; ks++) {
            uint32_t A0f[4], A1f[4];
            LDSM4(A0f, stage + OFF_A0 + a_off + ks * 32);
            LDSM4(A1f, stage + OFF_A0 + a_off + 16 * AROWB + ks * 32);
            uint32_t B0r[10];
            LDSM4T(&B0r[0], stage + OFF_B0 + b4_off + ks * 16 * BROWB);
            LDSM4T(&B0r[4], stage + OFF_B0 + b4_off + 32 + ks * 16 * BROWB);
            LDSM2T(&B0r[8], stage + OFF_B0 + b2_off + ks * 16 * BROWB);
#pragma unroll
            for (int f = 0; f < 5; f++) {
                MMA_F16(acc[0][f], A0f, B0r[2 * f], B0r[2 * f + 1]);
                MMA_F16(acc[1][f], A1f, B0r[2 * f], B0r[2 * f + 1]);
            }
        }

        cur = (cur + 1 == NSTAGES) ? 0 : cur + 1;
        nx2 = (nx2 + 1 == NSTAGES) ? 0 : nx2 + 1;
    }

    // Store tanh(-x) tile to g_C
    const int gid = lane >> 2, tig = lane & 3;
#pragma unroll
    for (int mf = 0; mf < 2; mf++) {
        const int row = m0 + wm * 32 + mf * 16 + gid;
        float* c0p = &g_C[(size_t)row * NN];
        float* c1p = &g_C[(size_t)(row + 8) * NN];
#pragma unroll
        for (int f = 0; f < 5; f++) {
            int col = n0 + wn * 40 + f * 8 + tig * 2;
            float2 lo, hi;
            lo.x = tanhf(-acc[mf][f][0]);
            lo.y = tanhf(-acc[mf][f][1]);
            hi.x = tanhf(-acc[mf][f][2]);
            hi.y = tanhf(-acc[mf][f][3]);
            *reinterpret_cast<float2*>(c0p + col) = lo;
            *reinterpret_cast<float2*>(c1p + col) = hi;
        }
    }

    // ---- Atomic handoff: third arriver combines this output region --------
    __shared__ int s_old;
    __syncthreads();
    const int yb = blockIdx.y % 3;       // t-band index within [0,384)
    if (tid == 0) {
        __threadfence();                 // release g_C tile
        s_old = atomicAdd(&g_cnt[yb][blockIdx.x], 1);
    }
    __syncthreads();

    if (s_old == 2) {
        __threadfence();                 // acquire peers' g_C tiles
        const int tb = yb * 128;         // 128 t-values in this band
        // 128 t x 80 j = 2560 float4 units, 10 per thread
#pragma unroll
        for (int q = 0; q < 10; q++) {
            int u   = tid + q * 256;
            int tt  = tb + u / 20;
            int js  = (u % 20) * 4;
            int jj  = n0 + js;
            int lag = tt >> 5;
            int b   = tt & 31;
            int jm  = jj % 200;

            float4 o4 = *reinterpret_cast<const float4*>(&g_C[(size_t)tt * NN + jj]);
            float4 a4 = *reinterpret_cast<const float4*>(&g_C[(size_t)(384 + tt) * NN + jj]);
            float4 n4 = *reinterpret_cast<const float4*>(&g_C[(size_t)(768 + tt) * NN + jj]);
            float4 lam = *reinterpret_cast<const float4*>(&lambd[lag * 200 + jm]);
            float4 lv  = *reinterpret_cast<const float4*>(&l[lag * 200 + jm]);

            float ib = 1.f / g_belta[lag];
            float pf = g_pf[lag];
            float c2 = g_c2[lag];

            float4 o;
            o.x = lam.x * ib * (pf * o4.x + 3.f * lv.x * (a4.x + c2 * n4.x));
            o.y = lam.y * ib * (pf * o4.y + 3.f * lv.y * (a4.y + c2 * n4.y));
            o.z = lam.z * ib * (pf * o4.z + 3.f * lv.z * (a4.z + c2 * n4.z));
            o.w = lam.w * ib * (pf * o4.w + 3.f * lv.w * (a4.w + c2 * n4.w));
            *reinterpret_cast<float4*>(
                &out[((size_t)b * NLAG + lag) * NN + jj]) = o;
        }
        __syncthreads();
        if (tid == 0) g_cnt[yb][blockIdx.x] = 0;   // reset for next replay
    }
}

// ---------------------------------------------------------------------------
extern "C" void kernel_launch(void* const* d_in, const int* in_sizes, int n_in,
                              void* d_out, int out_size) {
    const float* A          = (const float*)d_in[0];
    const float* WW         = (const float*)d_in[1];
    const float* train_init = (const float*)d_in[2];
    const float* alpha      = (const float*)d_in[3];
    const float* fract      = (const float*)d_in[4];
    const float* lambd      = (const float*)d_in[5];
    const float* l          = (const float*)d_in[6];
    float* out = (float*)d_out;

    cudaFuncSetAttribute(gemm_mma_kernel,
                         cudaFuncAttributeMaxDynamicSharedMemorySize,
                         NSTAGES * STAGE);

    prep_kernel<<<(PREP_TOTAL + 255) / 256, 256>>>(A, WW, train_init, alpha, fract);

    dim3 ggrid(NN / 80, MROWS / 128);             // (15, 9) = 135 CTAs, one wave
    gemm_mma_kernel<<<ggrid, 256, NSTAGES * STAGE>>>(lambd, l, out);
}

// round 16
// speedup vs baseline: 1.9740x; 1.1608x over previous
#include <cuda_runtime.h>
#include <cuda_fp16.h>
#include <math_constants.h>
#include <cstdint>

// Problem constants
#define NLAG   12
#define NB     32
#define NN     1200
#define MROWS  1152          // 3 * NLAG * NB
#define KDIM   1200
#define KP     1216          // K padded to 19*64
#define NP     1280          // B storage width (padded)

// GEMM tiling: CTA 128m x 80n, BK=64, 256 threads (8 warps = 4m x 2n, 32x40)
#define BK      64
#define NCHUNK  (KP / BK)    // 19
#define AROWB   144
#define BROWB   176
#define A_TILE  (128 * AROWB)    // 18432
#define B_TILE  (64 * BROWB)     // 11264
#define OFF_A0  0
#define OFF_B0  A_TILE
#define STAGE   (A_TILE + B_TILE)   // 29696
#define NSTAGES 3
#define NUNITS  1664

// Scratch (device globals; no allocation allowed)
__device__ __align__(16) __half g_A0[MROWS * KP];
__device__ __align__(16) __half g_B0[KP * NP];    // k-major
__device__ __align__(16) float g_C[MROWS * NN];
__device__ float g_belta[NLAG];
__device__ float g_c2[NLAG];
__device__ float g_pf[NLAG];

// ---------------------------------------------------------------------------
__device__ __forceinline__ uint32_t smem_u32(const void* p) {
    uint32_t a;
    asm("{ .reg .u64 t; cvta.to.shared.u64 t, %1; cvt.u32.u64 %0, t; }"
        : "=r"(a) : "l"(p));
    return a;
}

#define LDSM4(r, addr)                                                      \
    asm volatile("ldmatrix.sync.aligned.m8n8.x4.shared.b16 "                \
                 "{%0, %1, %2, %3}, [%4];"                                  \
                 : "=r"((r)[0]), "=r"((r)[1]), "=r"((r)[2]), "=r"((r)[3])   \
                 : "r"(addr))
#define LDSM4T(r, addr)                                                     \
    asm volatile("ldmatrix.sync.aligned.m8n8.x4.trans.shared.b16 "          \
                 "{%0, %1, %2, %3}, [%4];"                                  \
                 : "=r"((r)[0]), "=r"((r)[1]), "=r"((r)[2]), "=r"((r)[3])   \
                 : "r"(addr))
#define LDSM2T(r, addr)                                                     \
    asm volatile("ldmatrix.sync.aligned.m8n8.x2.trans.shared.b16 "          \
                 "{%0, %1}, [%2];"                                          \
                 : "=r"((r)[0]), "=r"((r)[1]) : "r"(addr))

#define MMA_F16(c, a, bb0, bb1)                                             \
    asm volatile("mma.sync.aligned.m16n8k16.row.col.f32.f16.f16.f32 "       \
                 "{%0, %1, %2, %3}, {%4, %5, %6, %7}, {%8, %9}, "           \
                 "{%0, %1, %2, %3};"                                        \
                 : "+f"((c)[0]), "+f"((c)[1]), "+f"((c)[2]), "+f"((c)[3])   \
                 : "r"((a)[0]), "r"((a)[1]), "r"((a)[2]), "r"((a)[3]),      \
                   "r"(bb0), "r"(bb1))

#define CP_ASYNC16(dst, src)                                                \
    asm volatile("cp.async.cg.shared.global [%0], [%1], 16;"                \
                 :: "r"(dst), "l"(__cvta_generic_to_global(src)))
#define CP_COMMIT() asm volatile("cp.async.commit_group;" ::: "memory")
#define CP_WAIT1()  asm volatile("cp.async.wait_group 1;" ::: "memory")
#define CP_WAIT0()  asm volatile("cp.async.wait_group 0;" ::: "memory")

// ---------------------------------------------------------------------------
__device__ __forceinline__ float gamma_fn(float x) {
    if (x > 0.f) return expf(lgammaf(x));
    return CUDART_PI_F / (sinf(CUDART_PI_F * x) * expf(lgammaf(1.f - x)));
}

__device__ __forceinline__ uint32_t pack4h(float a, float b, float c, float d,
                                           uint32_t& hi) {
    __half2 lo2 = __halves2half2(__float2half(a), __float2half(b));
    __half2 hi2 = __halves2half2(__float2half(c), __float2half(d));
    hi = *reinterpret_cast<uint32_t*>(&hi2);
    return *reinterpret_cast<uint32_t*>(&lo2);
}

// ---------------------------------------------------------------------------
// Fused prep (R11/R13 layout)
// ---------------------------------------------------------------------------
#define R0 (384 * KP / 4)
#define R1 (NB * NN / 2)
#define R2 (768 * (KP - KDIM) / 4)
#define R3 (KP * NP / 4)
#define PREP_TOTAL (R0 + R1 + R2 + R3)

__global__ void prep_kernel(const float* __restrict__ A,
                            const float* __restrict__ WW,
                            const float* __restrict__ train_init,
                            const float* __restrict__ alpha,
                            const float* __restrict__ fract) {
    int idx = blockIdx.x * blockDim.x + threadIdx.x;

    if (blockIdx.x == 0 && threadIdx.x < NLAG) {
        int lag = threadIdx.x;
        float a   = alpha[lag];
        float f   = fract[lag];
        float ga1 = gamma_fn(a + 1.f);
        float gm2 = gamma_fn(a - 2.f);
        float belta = 1.f
                    + ga1 / gamma_fn(a)
                    + ga1 / (2.f * gamma_fn(a - 1.f))
                    + ga1 / (6.f * gm2);
        g_belta[lag] = belta;
        g_c2[lag]    = ga1 / (6.f * gm2);
        g_pf[lag]    = 2.f * powf(3.f, f);
    }

    if (idx < R0) {
        int r = idx / (KP / 4);
        int k = (idx - r * (KP / 4)) * 4;
        float4 v = make_float4(0.f, 0.f, 0.f, 0.f);
        if (k < KDIM)
            v = *reinterpret_cast<const float4*>(&A[r * KDIM + k]);
        uint32_t hi, lo = pack4h(v.x, v.y, v.z, v.w, hi);
        reinterpret_cast<uint2*>(g_A0)[idx] = make_uint2(lo, hi);
    } else if (idx < R0 + R1) {
        int p = idx - R0;
        int b = p / (NN / 2);
        int i = (p - b * (NN / 2)) * 2;
        const float4* ti4 = reinterpret_cast<const float4*>(
            train_init + (size_t)(b * NN + i) * 26);
        float buf[52];
#pragma unroll
        for (int q = 0; q < 13; q++) {
            float4 v = ti4[q];
            buf[q * 4 + 0] = v.x; buf[q * 4 + 1] = v.y;
            buf[q * 4 + 2] = v.z; buf[q * 4 + 3] = v.w;
        }
#pragma unroll
        for (int j = 0; j < 13; j++) {
            __half2 h = __halves2half2(__float2half(buf[2 * j + 1]),
                                       __float2half(buf[26 + 2 * j + 1]));
            if (j >= 1) {
                int row = 384 + (j - 1) * NB + b;
                *reinterpret_cast<__half2*>(&g_A0[(size_t)row * KP + i]) = h;
            }
            if (j <= 11) {
                int row = 768 + j * NB + b;
                *reinterpret_cast<__half2*>(&g_A0[(size_t)row * KP + i]) = h;
            }
        }
    } else if (idx < R0 + R1 + R2) {
        int p = idx - R0 - R1;
        int padw = (KP - KDIM) / 4;
        int row = 384 + p / padw;
        int k   = KDIM + (p % padw) * 4;
        reinterpret_cast<uint2*>(&g_A0[(size_t)row * KP + k])[0] = make_uint2(0u, 0u);
    } else if (idx < PREP_TOTAL) {
        int p = idx - R0 - R1 - R2;
        int k = p / (NP / 4);
        int n = (p - k * (NP / 4)) * 4;
        float4 v = make_float4(0.f, 0.f, 0.f, 0.f);
        if (k < KDIM && n < NN)
            v = *reinterpret_cast<const float4*>(&WW[k * NN + n]);
        uint32_t hi, lo = pack4h(v.x, v.y, v.z, v.w, hi);
        reinterpret_cast<uint2*>(g_B0)[p] = make_uint2(lo, hi);
    }
}

// ---------------------------------------------------------------------------
// cp.async issue for one chunk: B 64x160B (640 units); A 128x128B (1024 units)
// ---------------------------------------------------------------------------
__device__ __forceinline__ void issue_chunk(uint32_t stage, int m0, int n0,
                                            int k0, int tid) {
#pragma unroll
    for (int i = 0; i < 7; i++) {
        int u = tid + i * 256;
        if (u < NUNITS) {
            uint32_t dst;
            const __half* src;
            if (u < 640) {
                int row = u / 10;
                int seg = u - row * 10;
                src = g_B0 + (size_t)(k0 + row) * NP + n0 + seg * 8;
                dst = stage + OFF_B0 + row * BROWB + seg * 16;
            } else {
                int v   = u - 640;
                int row = v >> 3;
                int seg = v & 7;
                src = g_A0 + (size_t)(m0 + row) * KP + k0 + seg * 8;
                dst = stage + OFF_A0 + row * AROWB + seg * 16;
            }
            CP_ASYNC16(dst, src);
        }
    }
}

// Fragment loader for one k-step
#define LOAD_FRAGS(buf, stage, ks)                                          \
    do {                                                                    \
        LDSM4(A0f[buf], (stage) + OFF_A0 + a_off + (ks) * 32);              \
        LDSM4(A1f[buf], (stage) + OFF_A0 + a_off + 16 * AROWB + (ks) * 32); \
        LDSM4T(&B0r[buf][0], (stage) + OFF_B0 + b4_off + (ks) * 16 * BROWB);\
        LDSM4T(&B0r[buf][4], (stage) + OFF_B0 + b4_off + 32 + (ks) * 16 * BROWB); \
        LDSM2T(&B0r[buf][8], (stage) + OFF_B0 + b2_off + (ks) * 16 * BROWB);\
    } while (0)

// ---------------------------------------------------------------------------
// fp16 HMMA GEMM with register fragment double-buffering.
// CTA 128x80, 8 warps (32m x 40n each), BK=64, 3-stage cp.async pipeline.
// Grid (15, 9) = 135 CTAs, one wave.
// ---------------------------------------------------------------------------
__global__ __launch_bounds__(256)
void gemm_mma_kernel() {
    extern __shared__ __align__(16) char smem[];
    const uint32_t sb = smem_u32(smem);
    const int tid  = threadIdx.x;
    const int lane = tid & 31;
    const int wid  = tid >> 5;
    const int wm   = wid & 3;
    const int wn   = wid >> 2;
    const int m0   = blockIdx.y * 128;
    const int n0   = blockIdx.x * 80;

    const int j = lane >> 3, rr = lane & 7;
    const uint32_t a_off  = (uint32_t)((wm * 32 + (j & 1) * 8 + rr) * AROWB + (j >> 1) * 16);
    const uint32_t b4_off = (uint32_t)(((j & 1) * 8 + rr) * BROWB + (j >> 1) * 16 + wn * 80);
    const uint32_t b2_off = (uint32_t)(((j & 1) * 8 + rr) * BROWB + wn * 80 + 64);

    float acc[2][5][4];
#pragma unroll
    for (int mf = 0; mf < 2; mf++)
#pragma unroll
        for (int f = 0; f < 5; f++)
#pragma unroll
            for (int e = 0; e < 4; e++) acc[mf][f][e] = 0.f;

    issue_chunk(sb + 0 * STAGE, m0, n0, 0, tid);
    CP_COMMIT();
    issue_chunk(sb + 1 * STAGE, m0, n0, BK, tid);
    CP_COMMIT();

    uint32_t A0f[2][4], A1f[2][4], B0r[2][10];

    int cur = 0, nx2 = 2;
    for (int c = 0; c < NCHUNK; c++) {
        if (c + 1 < NCHUNK) CP_WAIT1(); else CP_WAIT0();
        __syncthreads();

        if (c + 2 < NCHUNK) {
            issue_chunk(sb + (uint32_t)nx2 * STAGE, m0, n0, (c + 2) * BK, tid);
            CP_COMMIT();
        }

        const uint32_t stage = sb + (uint32_t)cur * STAGE;

        // Register double-buffered k-step pipeline
        LOAD_FRAGS(0, stage, 0);
#pragma unroll
        for (int ks = 0; ks < 4; ks++) {
            const int pf = ks & 1;
            if (ks < 3) LOAD_FRAGS(pf ^ 1, stage, ks + 1);
#pragma unroll
            for (int f = 0; f < 5; f++) {
                MMA_F16(acc[0][f], A0f[pf], B0r[pf][2 * f], B0r[pf][2 * f + 1]);
                MMA_F16(acc[1][f], A1f[pf], B0r[pf][2 * f], B0r[pf][2 * f + 1]);
            }
        }

        cur = (cur + 1 == NSTAGES) ? 0 : cur + 1;
        nx2 = (nx2 + 1 == NSTAGES) ? 0 : nx2 + 1;
    }

    // Store with fused tanh(-x); cols always < 1200 (grid.x*80 == NN).
    const int gid = lane >> 2, tig = lane & 3;
#pragma unroll
    for (int mf = 0; mf < 2; mf++) {
        const int row = m0 + wm * 32 + mf * 16 + gid;
        float* c0p = &g_C[(size_t)row * NN];
        float* c1p = &g_C[(size_t)(row + 8) * NN];
#pragma unroll
        for (int f = 0; f < 5; f++) {
            int col = n0 + wn * 40 + f * 8 + tig * 2;
            float2 lo, hi;
            lo.x = tanhf(-acc[mf][f][0]);
            lo.y = tanhf(-acc[mf][f][1]);
            hi.x = tanhf(-acc[mf][f][2]);
            hi.y = tanhf(-acc[mf][f][3]);
            *reinterpret_cast<float2*>(c0p + col) = lo;
            *reinterpret_cast<float2*>(c1p + col) = hi;
        }
    }
}

// ---------------------------------------------------------------------------
// Final combine (float4): out = lambd/belta * ( pf*OUT + 3*l*(A0NEW + c2*ANOLD) )
// ---------------------------------------------------------------------------
__global__ void epilogue_kernel(const float* __restrict__ lambd,
                                const float* __restrict__ l,
                                float* __restrict__ out) {
    int idx = blockIdx.x * blockDim.x + threadIdx.x;
    const int total4 = NB * NLAG * (NN / 4);
    if (idx >= total4) return;
    int j4  = (idx % (NN / 4)) * 4;
    int lag = (idx / (NN / 4)) % NLAG;
    int b   = idx / ((NN / 4) * NLAG);
    int jm  = j4 % 200;

    int r = lag * NB + b;
    float4 o4 = *reinterpret_cast<const float4*>(&g_C[(size_t)r * NN + j4]);
    float4 a4 = *reinterpret_cast<const float4*>(&g_C[(size_t)(384 + r) * NN + j4]);
    float4 n4 = *reinterpret_cast<const float4*>(&g_C[(size_t)(768 + r) * NN + j4]);
    float4 lam = *reinterpret_cast<const float4*>(&lambd[lag * 200 + jm]);
    float4 lv  = *reinterpret_cast<const float4*>(&l[lag * 200 + jm]);

    float ib = 1.f / g_belta[lag];
    float pf = g_pf[lag];
    float c2 = g_c2[lag];

    float4 o;
    o.x = lam.x * ib * (pf * o4.x + 3.f * lv.x * (a4.x + c2 * n4.x));
    o.y = lam.y * ib * (pf * o4.y + 3.f * lv.y * (a4.y + c2 * n4.y));
    o.z = lam.z * ib * (pf * o4.z + 3.f * lv.z * (a4.z + c2 * n4.z));
    o.w = lam.w * ib * (pf * o4.w + 3.f * lv.w * (a4.w + c2 * n4.w));
    *reinterpret_cast<float4*>(&out[(size_t)idx * 4]) = o;
}

// ---------------------------------------------------------------------------
extern "C" void kernel_launch(void* const* d_in, const int* in_sizes, int n_in,
                              void* d_out, int out_size) {
    const float* A          = (const float*)d_in[0];
    const float* WW         = (const float*)d_in[1];
    const float* train_init = (const float*)d_in[2];
    const float* alpha      = (const float*)d_in[3];
    const float* fract      = (const float*)d_in[4];
    const float* lambd      = (const float*)d_in[5];
    const float* l          = (const float*)d_in[6];
    float* out = (float*)d_out;

    cudaFuncSetAttribute(gemm_mma_kernel,
                         cudaFuncAttributeMaxDynamicSharedMemorySize,
                         NSTAGES * STAGE);

    prep_kernel<<<(PREP_TOTAL + 255) / 256, 256>>>(A, WW, train_init, alpha, fract);

    dim3 ggrid(NN / 80, MROWS / 128);             // (15, 9) = 135 CTAs, one wave
    gemm_mma_kernel<<<ggrid, 256, NSTAGES * STAGE>>>();

    const int total4 = NB * NLAG * (NN / 4);
    epilogue_kernel<<<(total4 + 255) / 256, 256>>>(lambd, l, out);
}